// round 11
// baseline (speedup 1.0000x reference)
#include <cuda_runtime.h>
#include <math.h>

#define Bb   16
#define Tt   512
#define Pdim 1024
#define Ddim 2048
#define G4   8192      // 4*D
#define LNEPS 1e-3f

#define NCTA 128       // persistent-scan grid (must all be co-resident; <= 148 SMs)
#define NTHR 256

// smem layout (float offsets) for scan kernel
#define SM_HSD    0        // phase A: H duplicated [16][1024] f32x2 = 32768 floats (128KB)
#define SM_GRED   32768    // phase A: partials [8][16][64] = 8192 floats
#define SM_HPART  32768    // phase B: partials [16][16][8] = 2048 floats (union w/ Gred)
#define SM_PWS    40960    // persistent Pw slice [2048][8] = 16384 floats
#define SM_FLOATS 57344
#define SM_BYTES  (SM_FLOATS * 4)   // 229376 B <= 227KB cap

// ---------------- scratch (static device globals; no allocation) -------------
__device__ float g_XG[(size_t)Bb * Tt * G4];        // 256 MB: pre-activations
__device__ float g_BUF[3][(size_t)Bb * Tt * Pdim];  // 3 x 32 MB ping-pong
__device__ float g_ST[Ddim * Bb];                   // s transposed [d][b]
__device__ float g_C[Bb * Ddim];                    // cell state
__device__ float g_H[Bb * Pdim];                    // hidden state

// grid barrier state
__device__ unsigned g_cnt = 0;
__device__ unsigned g_gen = 0;

__device__ __forceinline__ float sigm(float x) { return 1.0f / (1.0f + expf(-x)); }

// ---------------- packed f32x2 helpers (Blackwell) ---------------------------
__device__ __forceinline__ unsigned long long fma2(unsigned long long a,
                                                   unsigned long long b,
                                                   unsigned long long c) {
    unsigned long long d;
    asm("fma.rn.f32x2 %0, %1, %2, %3;" : "=l"(d) : "l"(a), "l"(b), "l"(c));
    return d;
}
__device__ __forceinline__ unsigned long long pack2(float lo, float hi) {
    unsigned long long r;
    asm("mov.b64 %0, {%1, %2};" : "=l"(r) : "f"(lo), "f"(hi));
    return r;
}
__device__ __forceinline__ float2 unpack2(unsigned long long v) {
    float2 r;
    asm("mov.b64 {%0, %1}, %2;" : "=f"(r.x), "=f"(r.y) : "l"(v));
    return r;
}

// ---------------- software grid barrier (acq/rel, no membar.gl on wait) ------
__device__ __forceinline__ void grid_sync() {
    __syncthreads();
    if (threadIdx.x == 0) {
        __threadfence();   // make this CTA's global writes visible before arrive
        unsigned gen;
        asm volatile("ld.global.u32 %0, [%1];" : "=r"(gen) : "l"(&g_gen));
        unsigned old;
        asm volatile("atom.add.acq_rel.gpu.global.u32 %0, [%1], 1;"
                     : "=r"(old) : "l"(&g_cnt));
        if (old == (unsigned)(NCTA - 1)) {
            asm volatile("st.global.u32 [%0], %1;" :: "l"(&g_cnt), "r"(0u));
            unsigned ng = gen + 1;
            asm volatile("st.release.gpu.global.u32 [%0], %1;" :: "l"(&g_gen), "r"(ng));
        } else {
            unsigned v;
            do {
                asm volatile("ld.acquire.gpu.global.u32 %0, [%1];" : "=r"(v) : "l"(&g_gen));
                if (v != gen) break;
                __nanosleep(20);
            } while (true);
        }
    }
    __syncthreads();
}

// ---------------- init states ------------------------------------------------
__global__ void k_init(const float* __restrict__ state) {
    int i = blockIdx.x * blockDim.x + threadIdx.x;
    if (i < Bb * Ddim) g_C[i] = state[i];
    if (i < Bb * Pdim) {
        int b = i / Pdim, p = i % Pdim;
        g_H[i] = state[Bb * Ddim + b * Ddim + p];
    }
}

// ---------------- big GEMM: C[M,N] = A @ W + bias ---------------------------
// 128x128x16 tiles, double-buffered smem, one sync per k-tile, 2 CTAs/SM.
// convmode==1: row r of A starts at ((r/511)*512 + r%511)*1024, spans 2048.
__global__ void __launch_bounds__(NTHR, 2) k_gemm(const float* __restrict__ A,
                                                  const float* __restrict__ W,
                                                  const float* __restrict__ bias,
                                                  float* __restrict__ C,
                                                  int M, int N, int K, int convmode) {
    __shared__ float As[2][16][132];
    __shared__ float Bs[2][16][128];

    int tid = threadIdx.x;
    int tx = tid & 15, ty = tid >> 4;
    int m0 = blockIdx.y * 128, n0 = blockIdx.x * 128;

    int ar = tid >> 1, ac = (tid & 1) * 8;      // A tile: 128 rows x 16 k
    int br = tid >> 4, bc = (tid & 15) * 8;     // B tile: 16 k x 128 n
    int r = m0 + ar;
    bool rok = (r < M);
    size_t abase = 0;
    if (rok) abase = convmode ? ((size_t)((r / 511) * 512 + (r % 511))) * (size_t)Pdim
                              : (size_t)r * (size_t)K;

    unsigned long long acc[8][4];
#pragma unroll
    for (int i = 0; i < 8; i++)
#pragma unroll
        for (int j = 0; j < 4; j++) acc[i][j] = 0ull;

    // prologue: tile 0 -> buf 0
    {
        float4 a0 = make_float4(0.f, 0.f, 0.f, 0.f), a1 = a0;
        if (rok) {
            a0 = *(const float4*)(A + abase + ac);
            a1 = *(const float4*)(A + abase + ac + 4);
        }
        float4 b0v = *(const float4*)(W + (size_t)br * N + n0 + bc);
        float4 b1v = *(const float4*)(W + (size_t)br * N + n0 + bc + 4);
#pragma unroll
        for (int j = 0; j < 4; j++) {
            As[0][ac + j][ar]     = (&a0.x)[j];
            As[0][ac + 4 + j][ar] = (&a1.x)[j];
        }
        *(float4*)&Bs[0][br][bc]     = b0v;
        *(float4*)&Bs[0][br][bc + 4] = b1v;
    }
    __syncthreads();

    int buf = 0;
    for (int k0 = 0; k0 < K; k0 += 16) {
        bool more = (k0 + 16) < K;
        float4 na0 = make_float4(0.f, 0.f, 0.f, 0.f), na1 = na0, nb0, nb1;
        if (more) {
            if (rok) {
                na0 = *(const float4*)(A + abase + k0 + 16 + ac);
                na1 = *(const float4*)(A + abase + k0 + 16 + ac + 4);
            }
            nb0 = *(const float4*)(W + (size_t)(k0 + 16 + br) * N + n0 + bc);
            nb1 = *(const float4*)(W + (size_t)(k0 + 16 + br) * N + n0 + bc + 4);
        }
#pragma unroll
        for (int kk = 0; kk < 16; kk++) {
            float4 av0 = *(const float4*)&As[buf][kk][ty * 8];
            float4 av1 = *(const float4*)&As[buf][kk][ty * 8 + 4];
            ulonglong2 bb0 = *(const ulonglong2*)&Bs[buf][kk][tx * 8];
            ulonglong2 bb1 = *(const ulonglong2*)&Bs[buf][kk][tx * 8 + 4];
            float aa[8] = {av0.x, av0.y, av0.z, av0.w, av1.x, av1.y, av1.z, av1.w};
#pragma unroll
            for (int i = 0; i < 8; i++) {
                unsigned long long ap = pack2(aa[i], aa[i]);
                acc[i][0] = fma2(ap, bb0.x, acc[i][0]);
                acc[i][1] = fma2(ap, bb0.y, acc[i][1]);
                acc[i][2] = fma2(ap, bb1.x, acc[i][2]);
                acc[i][3] = fma2(ap, bb1.y, acc[i][3]);
            }
        }
        if (more) {
            int nb = buf ^ 1;
#pragma unroll
            for (int j = 0; j < 4; j++) {
                As[nb][ac + j][ar]     = (&na0.x)[j];
                As[nb][ac + 4 + j][ar] = (&na1.x)[j];
            }
            *(float4*)&Bs[nb][br][bc]     = nb0;
            *(float4*)&Bs[nb][br][bc + 4] = nb1;
        }
        __syncthreads();
        buf ^= 1;
    }

#pragma unroll
    for (int i = 0; i < 8; i++) {
        int rr = m0 + ty * 8 + i;
        if (rr < M) {
            float* cp = C + (size_t)rr * (size_t)N + n0 + tx * 8;
            const float* bp = bias + n0 + tx * 8;
#pragma unroll
            for (int jj = 0; jj < 4; jj++) {
                float2 v = unpack2(acc[i][jj]);
                cp[jj * 2 + 0] = v.x + bp[jj * 2 + 0];
                cp[jj * 2 + 1] = v.y + bp[jj * 2 + 1];
            }
        }
    }
}

// ---------------- persistent scan: whole-layer LSTM recurrence ---------------
// 128 CTAs x 256 thr, all co-resident. CTA owns d-slice [cta*16, cta*16+16)
// for gates/cell, and p-slice [cta*8, cta*8+8) for the projection output.
// H staged pre-duplicated as f32x2 pairs -> phase A inner loop = LDS.64 + fma2.
// Pw slice persistent in smem. Phase B reads S^T straight from global.
__global__ void __launch_bounds__(NTHR, 1) k_scan(const float* __restrict__ Wh,
                                                  const float* __restrict__ Pw,
                                                  const float* __restrict__ XG,
                                                  float* __restrict__ RAW,
                                                  int T) {
    extern __shared__ float sm[];
    unsigned long long* Hsd = (unsigned long long*)(sm + SM_HSD);
    float* Gred  = sm + SM_GRED;
    float* Hpart = sm + SM_HPART;
    float* Pws   = sm + SM_PWS;

    const int tid = threadIdx.x;
    const int cta = blockIdx.x;
    const int d0 = cta * 16;   // gate d-slice
    const int p0 = cta * 8;    // proj col-slice

    // phase A compute mapping
    const int ks8  = tid >> 5;         // k-slice of 128 (0..7) — constant per warp
    const int lane = tid & 31;
    const int bh   = lane >> 4;        // b-half (8 b's)
    const int cq   = lane & 15;        // col-quad (4 cols within 64)
    const int gate = cq >> 2;
    const int j4 = (cq & 3) << 2;
    const float* wbase = Wh + (size_t)(ks8 * 128) * G4 + (size_t)gate * Ddim + d0 + j4;

    // gate/cell mapping: one (b, dl) tuple per thread
    const int gb = tid >> 4;
    const int dl = tid & 15;
    float c_reg = g_C[gb * Ddim + d0 + dl];

    // phase B mapping
    const int b2 = tid & 15;
    const int ks = tid >> 4;          // 16 k-splits of 128

    // ---- persistent Pw slice (constant over t) ----
    {
        const float* pwb = Pw + p0;
#pragma unroll 4
        for (int e = tid; e < 4096; e += NTHR) {
            int k = e >> 1, hf = (e & 1) * 4;
            *(float4*)&Pws[k * 8 + hf] =
                *(const float4*)(pwb + (size_t)k * Pdim + hf);
        }
    }
    __syncthreads();

    for (int t = 0; t < T; t++) {
        // ---- prefetch XG gates for this step (consumed after phase A) ----
        float xgv[4];
        {
            const float* xgp = XG + ((size_t)gb * T + t) * (size_t)G4 + d0 + dl;
#pragma unroll
            for (int g = 0; g < 4; g++) xgv[g] = xgp[(size_t)g * Ddim];
        }

        // ---- stage H into smem, duplicated as f32x2 pairs ----
#pragma unroll 4
        for (int i = tid; i < (Bb * Pdim) / 4; i += NTHR) {
            float4 v = ((const float4*)g_H)[i];
            ulonglong2 p0v, p1v;
            p0v.x = pack2(v.x, v.x); p0v.y = pack2(v.y, v.y);
            p1v.x = pack2(v.z, v.z); p1v.y = pack2(v.w, v.w);
            *(ulonglong2*)(Hsd + (size_t)i * 4)     = p0v;
            *(ulonglong2*)(Hsd + (size_t)i * 4 + 2) = p1v;
        }
        __syncthreads();

        // ---- phase A: partial G = H @ Wh over this thread's k-slice ----
        {
            unsigned long long acc[8][2];
#pragma unroll
            for (int i = 0; i < 8; i++) { acc[i][0] = 0ull; acc[i][1] = 0ull; }
            const unsigned long long* hb = Hsd + (size_t)(bh * 8) * 1024 + ks8 * 128;
            const float* wp = wbase;
            ulonglong2 wc0 = *(const ulonglong2*)(wp + 0 * (size_t)G4);
            ulonglong2 wc1 = *(const ulonglong2*)(wp + 1 * (size_t)G4);
            ulonglong2 wc2 = *(const ulonglong2*)(wp + 2 * (size_t)G4);
            ulonglong2 wc3 = *(const ulonglong2*)(wp + 3 * (size_t)G4);
#pragma unroll 1
            for (int k0 = 0; k0 < 128; k0 += 4) {
                ulonglong2 wn0, wn1, wn2, wn3;
                bool more = k0 < 124;
                if (more) {
                    const float* wq = wp + (size_t)(k0 + 4) * G4;
                    wn0 = *(const ulonglong2*)(wq + 0 * (size_t)G4);
                    wn1 = *(const ulonglong2*)(wq + 1 * (size_t)G4);
                    wn2 = *(const ulonglong2*)(wq + 2 * (size_t)G4);
                    wn3 = *(const ulonglong2*)(wq + 3 * (size_t)G4);
                }
#pragma unroll
                for (int b = 0; b < 8; b++) {
                    unsigned long long a0 = hb[(size_t)b * 1024 + k0 + 0];
                    acc[b][0] = fma2(a0, wc0.x, acc[b][0]);
                    acc[b][1] = fma2(a0, wc0.y, acc[b][1]);
                }
#pragma unroll
                for (int b = 0; b < 8; b++) {
                    unsigned long long a1 = hb[(size_t)b * 1024 + k0 + 1];
                    acc[b][0] = fma2(a1, wc1.x, acc[b][0]);
                    acc[b][1] = fma2(a1, wc1.y, acc[b][1]);
                }
#pragma unroll
                for (int b = 0; b < 8; b++) {
                    unsigned long long a2 = hb[(size_t)b * 1024 + k0 + 2];
                    acc[b][0] = fma2(a2, wc2.x, acc[b][0]);
                    acc[b][1] = fma2(a2, wc2.y, acc[b][1]);
                }
#pragma unroll
                for (int b = 0; b < 8; b++) {
                    unsigned long long a3 = hb[(size_t)b * 1024 + k0 + 3];
                    acc[b][0] = fma2(a3, wc3.x, acc[b][0]);
                    acc[b][1] = fma2(a3, wc3.y, acc[b][1]);
                }
                wc0 = wn0; wc1 = wn1; wc2 = wn2; wc3 = wn3;
            }
#pragma unroll
            for (int b = 0; b < 8; b++) {
                float2 v0 = unpack2(acc[b][0]);
                float2 v1 = unpack2(acc[b][1]);
                float* gp = Gred + ks8 * 1024 + (bh * 8 + b) * 64 + cq * 4;
                gp[0] = v0.x; gp[1] = v0.y; gp[2] = v1.x; gp[3] = v1.y;
            }
        }
        __syncthreads();

        // ---- gates + cell update (fused) ----
        {
            float gv[4];
#pragma unroll
            for (int g = 0; g < 4; g++) {
                float s = 0.0f;
#pragma unroll
                for (int sfrag = 0; sfrag < 8; sfrag++)
                    s += Gred[sfrag * 1024 + gb * 64 + g * 16 + dl];
                gv[g] = s + xgv[g];
            }
            float cc = sigm(gv[2] + 1.0f) * c_reg + sigm(gv[0]) * tanhf(gv[1]);
            c_reg = cc;
            float sv = sigm(gv[3]) * tanhf(cc);
            g_ST[(size_t)(d0 + dl) * Bb + gb] = sv;
        }

        grid_sync();

        // ---- phase B: H = S @ proj for this CTA's 8 output cols ----
        {
            unsigned long long acc[4] = {0ull, 0ull, 0ull, 0ull};
            const float* sg = g_ST + (size_t)(ks * 128) * Bb + b2;   // global, stride 16
            const float* pwk = Pws + ks * 128 * 8;
            float s0 = sg[0 * 16], s1 = sg[1 * 16], s2 = sg[2 * 16], s3 = sg[3 * 16];
#pragma unroll 1
            for (int k = 0; k < 128; k += 4) {
                float n0v, n1v, n2v, n3v;
                bool more = k < 124;
                if (more) {
                    const float* sq = sg + (size_t)(k + 4) * 16;
                    n0v = sq[0]; n1v = sq[16]; n2v = sq[32]; n3v = sq[48];
                }
#pragma unroll
                for (int u = 0; u < 4; u++) {
                    float s = (u == 0) ? s0 : (u == 1) ? s1 : (u == 2) ? s2 : s3;
                    unsigned long long sp = pack2(s, s);
                    ulonglong2 w0 = *(const ulonglong2*)(pwk + (k + u) * 8);
                    ulonglong2 w1 = *(const ulonglong2*)(pwk + (k + u) * 8 + 4);
                    acc[0] = fma2(sp, w0.x, acc[0]);
                    acc[1] = fma2(sp, w0.y, acc[1]);
                    acc[2] = fma2(sp, w1.x, acc[2]);
                    acc[3] = fma2(sp, w1.y, acc[3]);
                }
                s0 = n0v; s1 = n1v; s2 = n2v; s3 = n3v;
            }
            float* hp = Hpart + (ks * 16 + b2) * 8;
#pragma unroll
            for (int jj = 0; jj < 4; jj++) {
                float2 v = unpack2(acc[jj]);
                hp[jj * 2 + 0] = v.x;
                hp[jj * 2 + 1] = v.y;
            }
        }
        __syncthreads();
        if (tid < 128) {
            int b = tid >> 3, col = tid & 7;
            float h = 0.0f;
#pragma unroll
            for (int k2 = 0; k2 < 16; k2++)
                h += Hpart[(k2 * 16 + b) * 8 + col];
            g_H[b * Pdim + p0 + col] = h;
            RAW[((size_t)b * T + t) * (size_t)Pdim + p0 + col] = h;
        }

        grid_sync();
    }

    // write back final cell state
    g_C[gb * Ddim + d0 + dl] = c_reg;
}

// ---------------- layernorm over last dim (1024) ----------------------------
__global__ void k_ln(const float* __restrict__ X, float* __restrict__ Y,
                     const float* __restrict__ gamma, const float* __restrict__ beta) {
    __shared__ float red[256];
    int row = blockIdx.x;
    const float* x = X + (size_t)row * Pdim;
    float* y = Y + (size_t)row * Pdim;
    int tid = threadIdx.x;

    float s = 0.0f;
    for (int i = tid; i < Pdim; i += 256) s += x[i];
    red[tid] = s; __syncthreads();
    for (int o = 128; o > 0; o >>= 1) {
        if (tid < o) red[tid] += red[tid + o];
        __syncthreads();
    }
    float mean = red[0] * (1.0f / Pdim);
    __syncthreads();

    float v = 0.0f;
    for (int i = tid; i < Pdim; i += 256) { float d = x[i] - mean; v += d * d; }
    red[tid] = v; __syncthreads();
    for (int o = 128; o > 0; o >>= 1) {
        if (tid < o) red[tid] += red[tid + o];
        __syncthreads();
    }
    float rstd = rsqrtf(red[0] * (1.0f / Pdim) + LNEPS);
    __syncthreads();

    for (int i = tid; i < Pdim; i += 256)
        y[i] = (x[i] - mean) * rstd * gamma[i] + beta[i];
}

// ---------------- final c,h copy --------------------------------------------
__global__ void k_out_ch(float* __restrict__ oc, float* __restrict__ oh) {
    int idx = blockIdx.x * blockDim.x + threadIdx.x;
    if (idx < Bb * Ddim) oc[idx] = g_C[idx];
    if (idx < Bb * Pdim) oh[idx] = g_H[idx];
}

// ---------------- host driver -----------------------------------------------
extern "C" void kernel_launch(void* const* d_in, const int* in_sizes, int n_in,
                              void* d_out, int out_size) {
    const float* inputs  = (const float*)d_in[0];
    const float* state   = (const float*)d_in[1];
    const float* kernels = (const float*)d_in[2];
    const float* biases  = (const float*)d_in[3];
    const float* projs   = (const float*)d_in[4];
    const float* gamma   = (const float*)d_in[5];
    const float* beta    = (const float*)d_in[6];
    const float* convw   = (const float*)d_in[7];
    const float* convb   = (const float*)d_in[8];
    float* out = (float*)d_out;

    cudaFuncSetAttribute(k_scan, cudaFuncAttributeMaxDynamicSharedMemorySize,
                         SM_BYTES);

    float* BUF = nullptr;
    float* XG  = nullptr;
    cudaGetSymbolAddress((void**)&BUF, g_BUF);
    cudaGetSymbolAddress((void**)&XG, g_XG);
    const size_t BUFSZ = (size_t)Bb * Tt * Pdim;
    float* A  = BUF;
    float* Bu = BUF + BUFSZ;
    float* Cu = BUF + 2 * BUFSZ;

    k_init<<<(Bb * Ddim + 255) / 256, 256>>>(state);

    const float* cur = inputs;
    for (int l = 0; l < 4; l++) {
        int T = (l < 2) ? 512 : 511;
        int Mrows = Bb * T;
        const float* Wx = kernels + (size_t)l * 2 * Pdim * G4;
        const float* Wh = Wx + (size_t)Pdim * G4;
        const float* bi = biases + l * G4;
        const float* Pw = projs + (size_t)l * Ddim * Pdim;

        // pre-activations XG = cur @ Wx + bias
        dim3 gx(G4 / 128, (Mrows + 127) / 128);
        k_gemm<<<gx, NTHR>>>(cur, Wx, bi, XG, Mrows, G4, Pdim, 0);

        // whole-layer recurrence in ONE persistent launch
        k_scan<<<NCTA, NTHR, SM_BYTES>>>(Wh, Pw, XG, A, T);

        // layernorm
        float* LNout;
        if (l == 0)      LNout = Bu;
        else if (l == 1) LNout = Cu;
        else if (l == 2) LNout = Cu;
        else             LNout = out;
        k_ln<<<Mrows, 256>>>(A, LNout, gamma, beta);

        if (l == 1) {
            // temporal conv (window 2, VALID): GEMM with overlapped A rows
            int Mc = Bb * 511;
            dim3 gc(Pdim / 128, (Mc + 127) / 128);
            k_gemm<<<gc, NTHR>>>(Cu, convw, convb, Bu, Mc, Pdim, 2 * Pdim, 1);
            cur = Bu;
        } else if (l == 0) {
            cur = Bu;
        } else if (l == 2) {
            cur = Cu;
        }
    }

    // outputs: out [16,511,1024], then c [16,2048], then h [16,1024]
    size_t off_c = (size_t)Bb * 511 * Pdim;
    size_t off_h = off_c + (size_t)Bb * Ddim;
    k_out_ch<<<(Bb * Ddim + 255) / 256, 256>>>(out + off_c, out + off_h);
}